// round 14
// baseline (speedup 1.0000x reference)
#include <cuda_runtime.h>
#include <cuda_fp16.h>
#include <stdint.h>

// Model_63256278335531: 2-layer dual-GCN via fp16x2 mma.sync (HMMA) GEMMs.
// Big GEMM:   D = Ah*Bh + Ah*Bl   (A = adj/diff hi-only, B = fts hi+lo)
// Small GEMM: D = Ah*Bh + Al*Bh   (A = seq/h1 hi+lo,     B = W hi-only)
// R13: CTA 128x256, warp tile 64x64, 2-stage 80KB pipeline.

#define NEL_ADJ (8192ull*8192ull)
#define NEL_SEQ (8192ull*512ull)
#define NEL_W   (512ull*512ull)
#define NEL_FTS (8192ull*1024ull)

__device__ __align__(16) __half g_adjHi[NEL_ADJ];
__device__ __align__(16) __half g_difHi[NEL_ADJ];
__device__ __align__(16) __half g_spHi[NEL_SEQ], g_spLo[NEL_SEQ];
__device__ __align__(16) __half g_snHi[NEL_SEQ], g_snLo[NEL_SEQ];
__device__ __align__(16) __half g_wHi[4][NEL_W];
// fts as B of big GEMM: [K=8192][N=1024] (pos cols 0-511, neg 512-1023)
__device__ __align__(16) __half g_ftAHi[NEL_FTS], g_ftALo[NEL_FTS];
__device__ __align__(16) __half g_ftDHi[NEL_FTS], g_ftDLo[NEL_FTS];
// h1 packed [M=8192][1024]: A of layer-2 small GEMM
__device__ __align__(16) __half g_hAHi[NEL_FTS], g_hALo[NEL_FTS];
__device__ __align__(16) __half g_hDHi[NEL_FTS], g_hDLo[NEL_FTS];

__device__ __forceinline__ uint32_t smem_u32(const void* p){
    uint32_t a;
    asm("{ .reg .u64 t; cvta.to.shared.u64 t, %1; cvt.u32.u64 %0, t; }"
        : "=r"(a) : "l"(p));
    return a;
}
__device__ __forceinline__ void cp16(uint32_t dst, const void* src){
    asm volatile("{ .reg .u64 g; cvta.to.global.u64 g, %1;"
                 " cp.async.cg.shared.global [%0], [g], 16; }"
                 :: "r"(dst), "l"(src) : "memory");
}
__device__ __forceinline__ void cp_commit(){
    asm volatile("cp.async.commit_group;" ::: "memory");
}
__device__ __forceinline__ void cp_wait0(){
    asm volatile("cp.async.wait_group 0;" ::: "memory");
}
__device__ __forceinline__ void ldsm_x4(uint32_t& r0, uint32_t& r1,
                                        uint32_t& r2, uint32_t& r3, uint32_t a){
    asm volatile("ldmatrix.sync.aligned.m8n8.x4.shared.b16 {%0,%1,%2,%3}, [%4];"
                 : "=r"(r0), "=r"(r1), "=r"(r2), "=r"(r3) : "r"(a));
}
__device__ __forceinline__ void ldsm_x4_t(uint32_t& r0, uint32_t& r1,
                                          uint32_t& r2, uint32_t& r3, uint32_t a){
    asm volatile("ldmatrix.sync.aligned.m8n8.x4.trans.shared.b16 {%0,%1,%2,%3}, [%4];"
                 : "=r"(r0), "=r"(r1), "=r"(r2), "=r"(r3) : "r"(a));
}
__device__ __forceinline__ void mma16816(float* c, const uint32_t* a,
                                         uint32_t b0, uint32_t b1){
    asm volatile("mma.sync.aligned.m16n8k16.row.col.f32.f16.f16.f32 "
                 "{%0,%1,%2,%3}, {%4,%5,%6,%7}, {%8,%9}, {%0,%1,%2,%3};"
                 : "+f"(c[0]), "+f"(c[1]), "+f"(c[2]), "+f"(c[3])
                 : "r"(a[0]), "r"(a[1]), "r"(a[2]), "r"(a[3]), "r"(b0), "r"(b1));
}

// ---- fused conversion: adj/dif/W -> fp16 hi; seq -> fp16 hi+lo --------------
__device__ __forceinline__ void cv_hi(const float* __restrict__ x,
                                      __half* __restrict__ hi, size_t i)
{
    float4 v = *(const float4*)(x + i);
    __half2* H = (__half2*)(hi + i);
    H[0] = __halves2half2(__float2half_rn(v.x), __float2half_rn(v.y));
    H[1] = __halves2half2(__float2half_rn(v.z), __float2half_rn(v.w));
}
__device__ __forceinline__ void cv_hl(const float* __restrict__ x,
                                      __half* __restrict__ hi,
                                      __half* __restrict__ lo, size_t i)
{
    float4 v = *(const float4*)(x + i);
    __half h0 = __float2half_rn(v.x), h1 = __float2half_rn(v.y);
    __half h2 = __float2half_rn(v.z), h3 = __float2half_rn(v.w);
    __half l0 = __float2half_rn(v.x - __half2float(h0));
    __half l1 = __float2half_rn(v.y - __half2float(h1));
    __half l2 = __float2half_rn(v.z - __half2float(h2));
    __half l3 = __float2half_rn(v.w - __half2float(h3));
    __half2* H = (__half2*)(hi + i);
    H[0] = __halves2half2(h0, h1); H[1] = __halves2half2(h2, h3);
    __half2* L = (__half2*)(lo + i);
    L[0] = __halves2half2(l0, l1); L[1] = __halves2half2(l2, l3);
}

__global__ void fused_split(const float* __restrict__ adj, const float* __restrict__ dif,
                            const float* __restrict__ sp,  const float* __restrict__ sn,
                            const float* __restrict__ w0,  const float* __restrict__ w1,
                            const float* __restrict__ w2,  const float* __restrict__ w3,
                            __half* adjHi, __half* difHi,
                            __half* spHi, __half* spLo,
                            __half* snHi, __half* snLo, __half* wHi)
{
    size_t o = ((size_t)blockIdx.x * blockDim.x + threadIdx.x) * 4;
    if (o < NEL_ADJ) { cv_hi(adj, adjHi, o); return; } o -= NEL_ADJ;
    if (o < NEL_ADJ) { cv_hi(dif, difHi, o); return; } o -= NEL_ADJ;
    if (o < NEL_SEQ) { cv_hl(sp, spHi, spLo, o); return; } o -= NEL_SEQ;
    if (o < NEL_SEQ) { cv_hl(sn, snHi, snLo, o); return; } o -= NEL_SEQ;
    if (o < NEL_W) { cv_hi(w0, wHi + 0*NEL_W, o); return; } o -= NEL_W;
    if (o < NEL_W) { cv_hi(w1, wHi + 1*NEL_W, o); return; } o -= NEL_W;
    if (o < NEL_W) { cv_hi(w2, wHi + 2*NEL_W, o); return; } o -= NEL_W;
    if (o < NEL_W) { cv_hi(w3, wHi + 3*NEL_W, o); }
}

// ---- GEMM core --------------------------------------------------------------
// CTA 128(M) x 256(N), K-stage 64, 2-stage cp.async pipeline, 1 sync/iter.
// 8 warps: wm = wid&1 (M-halves of 64), wn = wid>>1 (4 N-quarters of 64).
// A rows 128B (8x16B units), B rows 512B (32x16B units); unit swizzle u^(r&7).
// big stage 80KB:  AH@0 (16K)  BH@16K (32K)  BL@48K (32K)
// small stage 64KB: AH@0 (16K) AL@16K (16K)  BH@32K (32K)
#define STG_BIG   81920
#define STG_SMALL 65536
#define SMEM_BIG   (2*STG_BIG)
#define SMEM_SMALL (2*STG_SMALL)

struct SmallArgs {
    const __half* Ahi[4]; const __half* Alo[4];
    long lda[4]; long aofs[4];
    const __half* Bhi[4];
    __half* Fhi[4]; __half* Flo[4];
    long fcol[4];
};
struct BigArgs {
    const __half* Ahi[2];
    const __half* Bhi[2]; const __half* Blo[2];
    float* C0[2]; float* C1[2];
    const float* bias[2]; const float* alphap[2];
    __half* Hhi[2]; __half* Hlo[2];
};

// small: fts[m*1024 + fcol + n] (hi/lo), A hi+lo, B = W hi, K=512, ldb=512
__global__ void __launch_bounds__(256, 1)
gemm_small(SmallArgs ar, int K, long ldb)
{
    extern __shared__ __align__(1024) char smem[];
    const uint32_t sbase = smem_u32(smem);
    const int z = blockIdx.z;
    const __half* __restrict__ Ahi = ar.Ahi[z];
    const __half* __restrict__ Alo = ar.Alo[z];
    const __half* __restrict__ Bhi = ar.Bhi[z];
    __half* __restrict__ Fhi = ar.Fhi[z];
    __half* __restrict__ Flo = ar.Flo[z];
    const long lda = ar.lda[z], aofs = ar.aofs[z], fcol = ar.fcol[z];

    const int tid  = threadIdx.x;
    const int lane = tid & 31;
    const int wid  = tid >> 5;
    const int wm   = wid & 1;
    const int wn   = wid >> 1;
    const long arow = (long)blockIdx.y * 128;
    const long bn0  = (long)blockIdx.x * 256;
    const int  nk   = K >> 6;

    auto load_stage = [&](int st, int kc){
        uint32_t base = sbase + st * STG_SMALL;
        const long ka = aofs + (long)kc * 64;
        const long kb = (long)kc * 64;
        #pragma unroll
        for (int s = 0; s < 4; ++s){
            int idx = tid + 256 * s;
            int r = idx >> 3, u = idx & 7;
            uint32_t sw = (uint32_t)(r * 128 + ((u ^ (r & 7)) << 4));
            cp16(base + sw,         Ahi + (arow + r) * lda + ka + u * 8);
            cp16(base + 16384 + sw, Alo + (arow + r) * lda + ka + u * 8);
        }
        #pragma unroll
        for (int s = 0; s < 8; ++s){
            int idx = tid + 256 * s;
            int r = idx >> 5, u = idx & 31;
            uint32_t sw = (uint32_t)(r * 512 + ((u ^ (r & 7)) << 4));
            cp16(base + 32768 + sw, Bhi + (kb + r) * ldb + bn0 + u * 8);
        }
        cp_commit();
    };

    float acc[4][8][4];
    #pragma unroll
    for (int i = 0; i < 4; ++i)
        #pragma unroll
        for (int j = 0; j < 8; ++j)
            #pragma unroll
            for (int q = 0; q < 4; ++q) acc[i][j][q] = 0.f;

    load_stage(0, 0);

    const int l16 = lane & 15, l2 = lane >> 4;
    const int bkr  = lane & 15;
    const int bnu0 = wn * 8;     // first 16B-unit of this warp's 64 N-cols

    for (int kt = 0; kt < nk; ++kt){
        cp_wait0();
        __syncthreads();
        if (kt + 1 < nk) load_stage((kt + 1) & 1, kt + 1);

        const uint32_t sb = sbase + (kt & 1) * STG_SMALL;
        #pragma unroll
        for (int ks = 0; ks < 4; ++ks){
            uint32_t aH[4][4], aL[4][4], bH[8][2];
            #pragma unroll
            for (int mt = 0; mt < 4; ++mt){
                int mr = wm * 64 + mt * 16 + l16;
                uint32_t ad = sb + mr * 128 + (((ks * 2 + l2) ^ (mr & 7)) << 4);
                ldsm_x4(aH[mt][0], aH[mt][1], aH[mt][2], aH[mt][3], ad);
                ldsm_x4(aL[mt][0], aL[mt][1], aL[mt][2], aL[mt][3], ad + 16384);
            }
            #pragma unroll
            for (int p = 0; p < 4; ++p){
                int kr = ks * 16 + bkr;
                int nu = bnu0 + p * 2 + l2;
                uint32_t ad = sb + 32768 + kr * 512 + ((nu ^ (kr & 7)) << 4);
                ldsm_x4_t(bH[2*p][0], bH[2*p][1], bH[2*p+1][0], bH[2*p+1][1], ad);
            }
            #pragma unroll
            for (int mt = 0; mt < 4; ++mt){
                #pragma unroll
                for (int nt = 0; nt < 8; ++nt)
                    mma16816(acc[mt][nt], aH[mt], bH[nt][0], bH[nt][1]);
                #pragma unroll
                for (int nt = 0; nt < 8; ++nt)
                    mma16816(acc[mt][nt], aL[mt], bH[nt][0], bH[nt][1]);
            }
        }
    }

    const int g  = lane >> 2;
    const int cp = (lane & 3) * 2;
    #pragma unroll
    for (int mt = 0; mt < 4; ++mt){
        #pragma unroll
        for (int nt = 0; nt < 8; ++nt){
            long n = fcol + bn0 + wn * 64 + nt * 8 + cp;
            #pragma unroll
            for (int h = 0; h < 2; ++h){
                long m = arow + wm * 64 + mt * 16 + g + h * 8;
                float v0 = acc[mt][nt][2*h + 0];
                float v1 = acc[mt][nt][2*h + 1];
                __half h0 = __float2half_rn(v0);
                __half h1 = __float2half_rn(v1);
                __half q0 = __float2half_rn(v0 - __half2float(h0));
                __half q1 = __float2half_rn(v1 - __half2float(h1));
                *(__half2*)&Fhi[m * 1024 + n] = __halves2half2(h0, h1);
                *(__half2*)&Flo[m * 1024 + n] = __halves2half2(q0, q1);
            }
        }
    }
}

// big: prelu(A@B + bias) -> fp32 C0/C1 (split at n=512), optional h1 hi/lo.
// A = adj/diff hi only, B = fts hi+lo. K=8192, lda=8192, ldb=1024.
__global__ void __launch_bounds__(256, 1)
gemm_big(BigArgs ar, int K)
{
    extern __shared__ __align__(1024) char smem[];
    const uint32_t sbase = smem_u32(smem);
    const int z = blockIdx.z;
    const __half* __restrict__ Ahi = ar.Ahi[z];
    const __half* __restrict__ Bhi = ar.Bhi[z];
    const __half* __restrict__ Blo = ar.Blo[z];
    float* __restrict__ C0 = ar.C0[z];
    float* __restrict__ C1 = ar.C1[z];
    const float* __restrict__ bias = ar.bias[z];
    const float* __restrict__ alphap = ar.alphap[z];
    __half* __restrict__ Hhi = ar.Hhi[z];
    __half* __restrict__ Hlo = ar.Hlo[z];
    const long lda = 8192, ldb = 1024;

    const int tid  = threadIdx.x;
    const int lane = tid & 31;
    const int wid  = tid >> 5;
    const int wm   = wid & 1;
    const int wn   = wid >> 1;
    const long arow = (long)blockIdx.y * 128;
    const long bn0  = (long)blockIdx.x * 256;
    const int  nk   = K >> 6;

    auto load_stage = [&](int st, int kc){
        uint32_t base = sbase + st * STG_BIG;
        const long ka = (long)kc * 64;
        const long kb = (long)kc * 64;
        #pragma unroll
        for (int s = 0; s < 4; ++s){
            int idx = tid + 256 * s;
            int r = idx >> 3, u = idx & 7;
            uint32_t sw = (uint32_t)(r * 128 + ((u ^ (r & 7)) << 4));
            cp16(base + sw, Ahi + (arow + r) * lda + ka + u * 8);
        }
        #pragma unroll
        for (int s = 0; s < 8; ++s){
            int idx = tid + 256 * s;
            int r = idx >> 5, u = idx & 31;
            uint32_t sw = (uint32_t)(r * 512 + ((u ^ (r & 7)) << 4));
            cp16(base + 16384 + sw, Bhi + (kb + r) * ldb + bn0 + u * 8);
            cp16(base + 49152 + sw, Blo + (kb + r) * ldb + bn0 + u * 8);
        }
        cp_commit();
    };

    float acc[4][8][4];
    #pragma unroll
    for (int i = 0; i < 4; ++i)
        #pragma unroll
        for (int j = 0; j < 8; ++j)
            #pragma unroll
            for (int q = 0; q < 4; ++q) acc[i][j][q] = 0.f;

    load_stage(0, 0);

    const int l16 = lane & 15, l2 = lane >> 4;
    const int bkr  = lane & 15;
    const int bnu0 = wn * 8;

    for (int kt = 0; kt < nk; ++kt){
        cp_wait0();
        __syncthreads();
        if (kt + 1 < nk) load_stage((kt + 1) & 1, kt + 1);

        const uint32_t sb = sbase + (kt & 1) * STG_BIG;
        #pragma unroll
        for (int ks = 0; ks < 4; ++ks){
            uint32_t aH[4][4], bH[8][2], bL[8][2];
            #pragma unroll
            for (int mt = 0; mt < 4; ++mt){
                int mr = wm * 64 + mt * 16 + l16;
                uint32_t ad = sb + mr * 128 + (((ks * 2 + l2) ^ (mr & 7)) << 4);
                ldsm_x4(aH[mt][0], aH[mt][1], aH[mt][2], aH[mt][3], ad);
            }
            #pragma unroll
            for (int p = 0; p < 4; ++p){
                int kr = ks * 16 + bkr;
                int nu = bnu0 + p * 2 + l2;
                uint32_t ad = sb + 16384 + kr * 512 + ((nu ^ (kr & 7)) << 4);
                ldsm_x4_t(bH[2*p][0], bH[2*p][1], bH[2*p+1][0], bH[2*p+1][1], ad);
                ldsm_x4_t(bL[2*p][0], bL[2*p][1], bL[2*p+1][0], bL[2*p+1][1], ad + 32768);
            }
            #pragma unroll
            for (int mt = 0; mt < 4; ++mt){
                #pragma unroll
                for (int nt = 0; nt < 8; ++nt)
                    mma16816(acc[mt][nt], aH[mt], bH[nt][0], bH[nt][1]);
                #pragma unroll
                for (int nt = 0; nt < 8; ++nt)
                    mma16816(acc[mt][nt], aH[mt], bL[nt][0], bL[nt][1]);
            }
        }
    }

    const int g  = lane >> 2;
    const int cp = (lane & 3) * 2;
    const float al = *alphap;
    #pragma unroll
    for (int mt = 0; mt < 4; ++mt){
        #pragma unroll
        for (int nt = 0; nt < 8; ++nt){
            long n  = bn0 + wn * 64 + nt * 8 + cp;
            int  nc = (int)(n & 511);
            float b0 = bias[nc], b1 = bias[nc + 1];
            float* C = (n < 512) ? C0 : C1;
            #pragma unroll
            for (int h = 0; h < 2; ++h){
                long m = arow + wm * 64 + mt * 16 + g + h * 8;
                float v0 = acc[mt][nt][2*h + 0] + b0;
                float v1 = acc[mt][nt][2*h + 1] + b1;
                v0 = (v0 >= 0.f) ? v0 : al * v0;
                v1 = (v1 >= 0.f) ? v1 : al * v1;
                *(float2*)&C[m * 512 + nc] = make_float2(v0, v1);
                if (Hhi){
                    __half h0 = __float2half_rn(v0);
                    __half h1 = __float2half_rn(v1);
                    __half q0 = __float2half_rn(v0 - __half2float(h0));
                    __half q1 = __float2half_rn(v1 - __half2float(h1));
                    *(__half2*)&Hhi[m * 1024 + n] = __halves2half2(h0, h1);
                    *(__half2*)&Hlo[m * 1024 + n] = __halves2half2(q0, q1);
                }
            }
        }
    }
}

extern "C" void kernel_launch(void* const* d_in, const int* in_sizes, int n_in,
                              void* d_out, int out_size)
{
    const float* seq_pos = (const float*)d_in[0];
    const float* seq_neg = (const float*)d_in[1];
    const float* adj     = (const float*)d_in[2];
    const float* diff    = (const float*)d_in[3];
    const float* W1a = (const float*)d_in[4];
    const float* W1d = (const float*)d_in[5];
    const float* W2a = (const float*)d_in[6];
    const float* W2d = (const float*)d_in[7];
    const float* b1a = (const float*)d_in[8];
    const float* b1d = (const float*)d_in[9];
    const float* b2a = (const float*)d_in[10];
    const float* b2d = (const float*)d_in[11];
    const float* al1a = (const float*)d_in[12];
    const float* al1d = (const float*)d_in[13];
    const float* al2a = (const float*)d_in[14];
    const float* al2d = (const float*)d_in[15];

    float* out = (float*)d_out;
    const size_t CHN = (size_t)8192 * 512;

    __half *adjHi,*difHi,*spHi,*spLo,*snHi,*snLo,*wHi;
    __half *ftAHi,*ftALo,*ftDHi,*ftDLo,*hAHi,*hALo,*hDHi,*hDLo;
    cudaGetSymbolAddress((void**)&adjHi, g_adjHi);
    cudaGetSymbolAddress((void**)&difHi, g_difHi);
    cudaGetSymbolAddress((void**)&spHi,  g_spHi);
    cudaGetSymbolAddress((void**)&spLo,  g_spLo);
    cudaGetSymbolAddress((void**)&snHi,  g_snHi);
    cudaGetSymbolAddress((void**)&snLo,  g_snLo);
    cudaGetSymbolAddress((void**)&wHi,   g_wHi);
    cudaGetSymbolAddress((void**)&ftAHi, g_ftAHi);
    cudaGetSymbolAddress((void**)&ftALo, g_ftALo);
    cudaGetSymbolAddress((void**)&ftDHi, g_ftDHi);
    cudaGetSymbolAddress((void**)&ftDLo, g_ftDLo);
    cudaGetSymbolAddress((void**)&hAHi,  g_hAHi);
    cudaGetSymbolAddress((void**)&hALo,  g_hALo);
    cudaGetSymbolAddress((void**)&hDHi,  g_hDHi);
    cudaGetSymbolAddress((void**)&hDLo,  g_hDLo);

    cudaFuncSetAttribute(gemm_small, cudaFuncAttributeMaxDynamicSharedMemorySize, SMEM_SMALL);
    cudaFuncSetAttribute(gemm_big,   cudaFuncAttributeMaxDynamicSharedMemorySize, SMEM_BIG);

    // one fused conversion launch
    {
        size_t total_vec4 = (2*NEL_ADJ + 2*NEL_SEQ + 4*NEL_W) / 4;
        int blocks = (int)((total_vec4 + 255) / 256);
        fused_split<<<blocks, 256>>>(adj, diff, seq_pos, seq_neg, W1a, W1d, W2a, W2d,
                                     adjHi, difHi, spHi, spLo, snHi, snLo, wHi);
    }

    dim3 blk(256);
    dim3 gS(2, 64, 4);   // N=512, 256-wide tiles, 4 small gemms batched
    dim3 gB(4, 64, 2);   // N=1024, 256-wide tiles, 2 big gemms batched

    // layer 1 small: fts = seq @ W1 (pos cols 0-511, neg 512-1023)
    {
        SmallArgs a;
        a.Ahi[0]=spHi; a.Alo[0]=spLo; a.Ahi[1]=snHi; a.Alo[1]=snLo;
        a.Ahi[2]=spHi; a.Alo[2]=spLo; a.Ahi[3]=snHi; a.Alo[3]=snLo;
        for (int i=0;i<4;++i){ a.lda[i]=512; a.aofs[i]=0; }
        a.Bhi[0]=wHi+0*NEL_W; a.Bhi[1]=wHi+0*NEL_W;
        a.Bhi[2]=wHi+1*NEL_W; a.Bhi[3]=wHi+1*NEL_W;
        a.Fhi[0]=ftAHi; a.Flo[0]=ftALo; a.Fhi[1]=ftAHi; a.Flo[1]=ftALo;
        a.Fhi[2]=ftDHi; a.Flo[2]=ftDLo; a.Fhi[3]=ftDHi; a.Flo[3]=ftDLo;
        a.fcol[0]=0; a.fcol[1]=512; a.fcol[2]=0; a.fcol[3]=512;
        gemm_small<<<gS, blk, SMEM_SMALL>>>(a, 512, 512);
    }

    // layer 1 big: h1 = prelu(A @ fts + b), also emit h1 fp16 hi/lo
    {
        BigArgs a;
        a.Ahi[0]=adjHi; a.Ahi[1]=difHi;
        a.Bhi[0]=ftAHi; a.Blo[0]=ftALo; a.Bhi[1]=ftDHi; a.Blo[1]=ftDLo;
        a.C0[0]=out+0*CHN; a.C1[0]=out+4*CHN;
        a.C0[1]=out+1*CHN; a.C1[1]=out+5*CHN;
        a.bias[0]=b1a; a.alphap[0]=al1a; a.bias[1]=b1d; a.alphap[1]=al1d;
        a.Hhi[0]=hAHi; a.Hlo[0]=hALo; a.Hhi[1]=hDHi; a.Hlo[1]=hDLo;
        gemm_big<<<gB, blk, SMEM_BIG>>>(a, 8192);
    }

    // layer 2 small: fts2 = h1 @ W2
    {
        SmallArgs a;
        a.Ahi[0]=hAHi; a.Alo[0]=hALo; a.Ahi[1]=hAHi; a.Alo[1]=hALo;
        a.Ahi[2]=hDHi; a.Alo[2]=hDLo; a.Ahi[3]=hDHi; a.Alo[3]=hDLo;
        for (int i=0;i<4;++i) a.lda[i]=1024;
        a.aofs[0]=0; a.aofs[1]=512; a.aofs[2]=0; a.aofs[3]=512;
        a.Bhi[0]=wHi+2*NEL_W; a.Bhi[1]=wHi+2*NEL_W;
        a.Bhi[2]=wHi+3*NEL_W; a.Bhi[3]=wHi+3*NEL_W;
        a.Fhi[0]=ftAHi; a.Flo[0]=ftALo; a.Fhi[1]=ftAHi; a.Flo[1]=ftALo;
        a.Fhi[2]=ftDHi; a.Flo[2]=ftDLo; a.Fhi[3]=ftDHi; a.Flo[3]=ftDLo;
        a.fcol[0]=0; a.fcol[1]=512; a.fcol[2]=0; a.fcol[3]=512;
        gemm_small<<<gS, blk, SMEM_SMALL>>>(a, 512, 512);
    }

    // layer 2 big
    {
        BigArgs a;
        a.Ahi[0]=adjHi; a.Ahi[1]=difHi;
        a.Bhi[0]=ftAHi; a.Blo[0]=ftALo; a.Bhi[1]=ftDHi; a.Blo[1]=ftDLo;
        a.C0[0]=out+2*CHN; a.C1[0]=out+6*CHN;
        a.C0[1]=out+3*CHN; a.C1[1]=out+7*CHN;
        a.bias[0]=b2a; a.alphap[0]=al2a; a.bias[1]=b2d; a.alphap[1]=al2d;
        a.Hhi[0]=nullptr; a.Hlo[0]=nullptr; a.Hhi[1]=nullptr; a.Hlo[1]=nullptr;
        gemm_big<<<gB, blk, SMEM_BIG>>>(a, 8192);
    }
}

// round 15
// speedup vs baseline: 1.8492x; 1.8492x over previous
#include <cuda_runtime.h>
#include <cuda_fp16.h>
#include <stdint.h>

// Model_63256278335531: 2-layer dual-GCN via fp16 mma.sync (HMMA) GEMMs.
// Big GEMM:   D = Ah*Bh            (A = adj/diff fp16, B = fts fp16)
// Small GEMM: D = Ah*Bh + Al*Bh    (A = seq/h1 hi+lo,  B = W fp16)
// fp32 register accumulate. R15: big GEMM single-term, 32KB stage, 2 CTAs/SM.

#define NEL_ADJ (8192ull*8192ull)
#define NEL_SEQ (8192ull*512ull)
#define NEL_W   (512ull*512ull)
#define NEL_FTS (8192ull*1024ull)

__device__ __align__(16) __half g_adjHi[NEL_ADJ];
__device__ __align__(16) __half g_difHi[NEL_ADJ];
__device__ __align__(16) __half g_spHi[NEL_SEQ], g_spLo[NEL_SEQ];
__device__ __align__(16) __half g_snHi[NEL_SEQ], g_snLo[NEL_SEQ];
__device__ __align__(16) __half g_wHi[4][NEL_W];
// fts as B of big GEMM: [K=8192][N=1024] (pos cols 0-511, neg 512-1023)
__device__ __align__(16) __half g_ftAHi[NEL_FTS];
__device__ __align__(16) __half g_ftDHi[NEL_FTS];
// h1 packed [M=8192][1024]: A of layer-2 small GEMM (hi + lo correction)
__device__ __align__(16) __half g_hAHi[NEL_FTS], g_hALo[NEL_FTS];
__device__ __align__(16) __half g_hDHi[NEL_FTS], g_hDLo[NEL_FTS];

__device__ __forceinline__ uint32_t smem_u32(const void* p){
    uint32_t a;
    asm("{ .reg .u64 t; cvta.to.shared.u64 t, %1; cvt.u32.u64 %0, t; }"
        : "=r"(a) : "l"(p));
    return a;
}
__device__ __forceinline__ void cp16(uint32_t dst, const void* src){
    asm volatile("{ .reg .u64 g; cvta.to.global.u64 g, %1;"
                 " cp.async.cg.shared.global [%0], [g], 16; }"
                 :: "r"(dst), "l"(src) : "memory");
}
__device__ __forceinline__ void cp_commit(){
    asm volatile("cp.async.commit_group;" ::: "memory");
}
__device__ __forceinline__ void cp_wait1(){
    asm volatile("cp.async.wait_group 1;" ::: "memory");
}
__device__ __forceinline__ void ldsm_x4(uint32_t& r0, uint32_t& r1,
                                        uint32_t& r2, uint32_t& r3, uint32_t a){
    asm volatile("ldmatrix.sync.aligned.m8n8.x4.shared.b16 {%0,%1,%2,%3}, [%4];"
                 : "=r"(r0), "=r"(r1), "=r"(r2), "=r"(r3) : "r"(a));
}
__device__ __forceinline__ void ldsm_x4_t(uint32_t& r0, uint32_t& r1,
                                          uint32_t& r2, uint32_t& r3, uint32_t a){
    asm volatile("ldmatrix.sync.aligned.m8n8.x4.trans.shared.b16 {%0,%1,%2,%3}, [%4];"
                 : "=r"(r0), "=r"(r1), "=r"(r2), "=r"(r3) : "r"(a));
}
__device__ __forceinline__ void mma16816(float* c, const uint32_t* a,
                                         uint32_t b0, uint32_t b1){
    asm volatile("mma.sync.aligned.m16n8k16.row.col.f32.f16.f16.f32 "
                 "{%0,%1,%2,%3}, {%4,%5,%6,%7}, {%8,%9}, {%0,%1,%2,%3};"
                 : "+f"(c[0]), "+f"(c[1]), "+f"(c[2]), "+f"(c[3])
                 : "r"(a[0]), "r"(a[1]), "r"(a[2]), "r"(a[3]), "r"(b0), "r"(b1));
}

// ---- fused conversion: adj/dif/W -> fp16 hi; seq -> fp16 hi+lo --------------
__device__ __forceinline__ void cv_hi(const float* __restrict__ x,
                                      __half* __restrict__ hi, size_t i)
{
    float4 v = *(const float4*)(x + i);
    __half2* H = (__half2*)(hi + i);
    H[0] = __halves2half2(__float2half_rn(v.x), __float2half_rn(v.y));
    H[1] = __halves2half2(__float2half_rn(v.z), __float2half_rn(v.w));
}
__device__ __forceinline__ void cv_hl(const float* __restrict__ x,
                                      __half* __restrict__ hi,
                                      __half* __restrict__ lo, size_t i)
{
    float4 v = *(const float4*)(x + i);
    __half h0 = __float2half_rn(v.x), h1 = __float2half_rn(v.y);
    __half h2 = __float2half_rn(v.z), h3 = __float2half_rn(v.w);
    __half l0 = __float2half_rn(v.x - __half2float(h0));
    __half l1 = __float2half_rn(v.y - __half2float(h1));
    __half l2 = __float2half_rn(v.z - __half2float(h2));
    __half l3 = __float2half_rn(v.w - __half2float(h3));
    __half2* H = (__half2*)(hi + i);
    H[0] = __halves2half2(h0, h1); H[1] = __halves2half2(h2, h3);
    __half2* L = (__half2*)(lo + i);
    L[0] = __halves2half2(l0, l1); L[1] = __halves2half2(l2, l3);
}

__global__ void fused_split(const float* __restrict__ adj, const float* __restrict__ dif,
                            const float* __restrict__ sp,  const float* __restrict__ sn,
                            const float* __restrict__ w0,  const float* __restrict__ w1,
                            const float* __restrict__ w2,  const float* __restrict__ w3,
                            __half* adjHi, __half* difHi,
                            __half* spHi, __half* spLo,
                            __half* snHi, __half* snLo, __half* wHi)
{
    size_t o = ((size_t)blockIdx.x * blockDim.x + threadIdx.x) * 4;
    if (o < NEL_ADJ) { cv_hi(adj, adjHi, o); return; } o -= NEL_ADJ;
    if (o < NEL_ADJ) { cv_hi(dif, difHi, o); return; } o -= NEL_ADJ;
    if (o < NEL_SEQ) { cv_hl(sp, spHi, spLo, o); return; } o -= NEL_SEQ;
    if (o < NEL_SEQ) { cv_hl(sn, snHi, snLo, o); return; } o -= NEL_SEQ;
    if (o < NEL_W) { cv_hi(w0, wHi + 0*NEL_W, o); return; } o -= NEL_W;
    if (o < NEL_W) { cv_hi(w1, wHi + 1*NEL_W, o); return; } o -= NEL_W;
    if (o < NEL_W) { cv_hi(w2, wHi + 2*NEL_W, o); return; } o -= NEL_W;
    if (o < NEL_W) { cv_hi(w3, wHi + 3*NEL_W, o); }
}

// ---- GEMM core --------------------------------------------------------------
// CTA 128(M) x 128(N), K-stage 64, 3-stage cp.async pipeline, 1 sync/iter.
// 8 warps: wm = wid&1 (M-halves of 64), wn = wid>>1 (4 N-quarters of 32).
// A rows 128B (8x16B units), B rows 256B (16x16B units); unit swizzle u^(r&7).
// big stage 32KB:  AH@0 (16K)  BH@16K (16K)        -> 3 stages = 96KB, 2 CTA/SM
// small stage 48KB: AH@0 (16K) AL@16K (16K) BH@32K -> 3 stages = 144KB, 1 CTA/SM
#define STG_BIG   32768
#define STG_SMALL 49152
#define SMEM_BIG   (3*STG_BIG)
#define SMEM_SMALL (3*STG_SMALL)

struct SmallArgs {
    const __half* Ahi[4]; const __half* Alo[4];
    long lda[4]; long aofs[4];
    const __half* Bhi[4];
    __half* Fhi[4];
    long fcol[4];
};
struct BigArgs {
    const __half* Ahi[2];
    const __half* Bhi[2];
    float* C0[2]; float* C1[2];
    const float* bias[2]; const float* alphap[2];
    __half* Hhi[2]; __half* Hlo[2];
};

// small: fts[m*1024 + fcol + n] (hi only), A hi+lo, B = W hi, K=512, ldb=512
__global__ void __launch_bounds__(256, 1)
gemm_small(SmallArgs ar, int K, long ldb)
{
    extern __shared__ __align__(1024) char smem[];
    const uint32_t sbase = smem_u32(smem);
    const int z = blockIdx.z;
    const __half* __restrict__ Ahi = ar.Ahi[z];
    const __half* __restrict__ Alo = ar.Alo[z];
    const __half* __restrict__ Bhi = ar.Bhi[z];
    __half* __restrict__ Fhi = ar.Fhi[z];
    const long lda = ar.lda[z], aofs = ar.aofs[z], fcol = ar.fcol[z];

    const int tid  = threadIdx.x;
    const int lane = tid & 31;
    const int wid  = tid >> 5;
    const int wm   = wid & 1;
    const int wn   = wid >> 1;
    const long arow = (long)blockIdx.y * 128;
    const long bn0  = (long)blockIdx.x * 128;
    const int  nk   = K >> 6;

    auto load_stage = [&](int st, int kc){
        uint32_t base = sbase + st * STG_SMALL;
        const long ka = aofs + (long)kc * 64;
        const long kb = (long)kc * 64;
        #pragma unroll
        for (int s = 0; s < 4; ++s){
            int idx = tid + 256 * s;
            int r = idx >> 3, u = idx & 7;
            uint32_t sw = (uint32_t)(r * 128 + ((u ^ (r & 7)) << 4));
            cp16(base + sw,         Ahi + (arow + r) * lda + ka + u * 8);
            cp16(base + 16384 + sw, Alo + (arow + r) * lda + ka + u * 8);
        }
        #pragma unroll
        for (int s = 0; s < 4; ++s){
            int idx = tid + 256 * s;
            int r = idx >> 4, u = idx & 15;
            uint32_t sw = (uint32_t)(r * 256 + ((u ^ (r & 7)) << 4));
            cp16(base + 32768 + sw, Bhi + (kb + r) * ldb + bn0 + u * 8);
        }
        cp_commit();
    };

    float acc[4][4][4];
    #pragma unroll
    for (int i = 0; i < 4; ++i)
        #pragma unroll
        for (int j = 0; j < 4; ++j)
            #pragma unroll
            for (int q = 0; q < 4; ++q) acc[i][j][q] = 0.f;

    load_stage(0, 0);
    load_stage(1, 1);

    const int l16 = lane & 15, l2 = lane >> 4;
    const int bkr  = lane & 15;
    const int bnu0 = (wn * 32) >> 3;

    for (int kt = 0; kt < nk; ++kt){
        cp_wait1();
        __syncthreads();
        if (kt + 2 < nk) load_stage((kt + 2) % 3, kt + 2);
        else cp_commit();

        const uint32_t sb = sbase + (kt % 3) * STG_SMALL;
        #pragma unroll
        for (int ks = 0; ks < 4; ++ks){
            uint32_t aH[4][4], aL[4][4], bH[4][2];
            #pragma unroll
            for (int mt = 0; mt < 4; ++mt){
                int mr = wm * 64 + mt * 16 + l16;
                uint32_t ad = sb + mr * 128 + (((ks * 2 + l2) ^ (mr & 7)) << 4);
                ldsm_x4(aH[mt][0], aH[mt][1], aH[mt][2], aH[mt][3], ad);
                ldsm_x4(aL[mt][0], aL[mt][1], aL[mt][2], aL[mt][3], ad + 16384);
            }
            #pragma unroll
            for (int p = 0; p < 2; ++p){
                int kr = ks * 16 + bkr;
                int nu = bnu0 + p * 2 + l2;
                uint32_t ad = sb + 32768 + kr * 256 + ((nu ^ (kr & 7)) << 4);
                ldsm_x4_t(bH[2*p][0], bH[2*p][1], bH[2*p+1][0], bH[2*p+1][1], ad);
            }
            #pragma unroll
            for (int mt = 0; mt < 4; ++mt){
                #pragma unroll
                for (int nt = 0; nt < 4; ++nt)
                    mma16816(acc[mt][nt], aH[mt], bH[nt][0], bH[nt][1]);
                #pragma unroll
                for (int nt = 0; nt < 4; ++nt)
                    mma16816(acc[mt][nt], aL[mt], bH[nt][0], bH[nt][1]);
            }
        }
    }

    const int g  = lane >> 2;
    const int cp = (lane & 3) * 2;
    #pragma unroll
    for (int mt = 0; mt < 4; ++mt){
        #pragma unroll
        for (int nt = 0; nt < 4; ++nt){
            long n = fcol + bn0 + wn * 32 + nt * 8 + cp;
            #pragma unroll
            for (int h = 0; h < 2; ++h){
                long m = arow + wm * 64 + mt * 16 + g + h * 8;
                float v0 = acc[mt][nt][2*h + 0];
                float v1 = acc[mt][nt][2*h + 1];
                *(__half2*)&Fhi[m * 1024 + n] =
                    __halves2half2(__float2half_rn(v0), __float2half_rn(v1));
            }
        }
    }
}

// big: prelu(A@B + bias) -> fp32 C0/C1 (split at n=512), optional h1 hi/lo.
// A = adj/diff fp16, B = fts fp16 (single term). K=8192, lda=8192, ldb=1024.
__global__ void __launch_bounds__(256, 2)
gemm_big(BigArgs ar, int K)
{
    extern __shared__ __align__(1024) char smem[];
    const uint32_t sbase = smem_u32(smem);
    const int z = blockIdx.z;
    const __half* __restrict__ Ahi = ar.Ahi[z];
    const __half* __restrict__ Bhi = ar.Bhi[z];
    float* __restrict__ C0 = ar.C0[z];
    float* __restrict__ C1 = ar.C1[z];
    const float* __restrict__ bias = ar.bias[z];
    const float* __restrict__ alphap = ar.alphap[z];
    __half* __restrict__ Hhi = ar.Hhi[z];
    __half* __restrict__ Hlo = ar.Hlo[z];
    const long lda = 8192, ldb = 1024;

    const int tid  = threadIdx.x;
    const int lane = tid & 31;
    const int wid  = tid >> 5;
    const int wm   = wid & 1;
    const int wn   = wid >> 1;
    const long arow = (long)blockIdx.y * 128;
    const long bn0  = (long)blockIdx.x * 128;
    const int  nk   = K >> 6;

    auto load_stage = [&](int st, int kc){
        uint32_t base = sbase + st * STG_BIG;
        const long ka = (long)kc * 64;
        const long kb = (long)kc * 64;
        #pragma unroll
        for (int s = 0; s < 4; ++s){
            int idx = tid + 256 * s;
            int r = idx >> 3, u = idx & 7;
            uint32_t sw = (uint32_t)(r * 128 + ((u ^ (r & 7)) << 4));
            cp16(base + sw, Ahi + (arow + r) * lda + ka + u * 8);
        }
        #pragma unroll
        for (int s = 0; s < 4; ++s){
            int idx = tid + 256 * s;
            int r = idx >> 4, u = idx & 15;
            uint32_t sw = (uint32_t)(r * 256 + ((u ^ (r & 7)) << 4));
            cp16(base + 16384 + sw, Bhi + (kb + r) * ldb + bn0 + u * 8);
        }
        cp_commit();
    };

    float acc[4][4][4];
    #pragma unroll
    for (int i = 0; i < 4; ++i)
        #pragma unroll
        for (int j = 0; j < 4; ++j)
            #pragma unroll
            for (int q = 0; q < 4; ++q) acc[i][j][q] = 0.f;

    load_stage(0, 0);
    load_stage(1, 1);

    const int l16 = lane & 15, l2 = lane >> 4;
    const int bkr  = lane & 15;
    const int bnu0 = (wn * 32) >> 3;

    for (int kt = 0; kt < nk; ++kt){
        cp_wait1();
        __syncthreads();
        if (kt + 2 < nk) load_stage((kt + 2) % 3, kt + 2);
        else cp_commit();

        const uint32_t sb = sbase + (kt % 3) * STG_BIG;
        #pragma unroll
        for (int ks = 0; ks < 4; ++ks){
            uint32_t aH[4][4], bH[4][2];
            #pragma unroll
            for (int mt = 0; mt < 4; ++mt){
                int mr = wm * 64 + mt * 16 + l16;
                uint32_t ad = sb + mr * 128 + (((ks * 2 + l2) ^ (mr & 7)) << 4);
                ldsm_x4(aH[mt][0], aH[mt][1], aH[mt][2], aH[mt][3], ad);
            }
            #pragma unroll
            for (int p = 0; p < 2; ++p){
                int kr = ks * 16 + bkr;
                int nu = bnu0 + p * 2 + l2;
                uint32_t ad = sb + 16384 + kr * 256 + ((nu ^ (kr & 7)) << 4);
                ldsm_x4_t(bH[2*p][0], bH[2*p][1], bH[2*p+1][0], bH[2*p+1][1], ad);
            }
            #pragma unroll
            for (int mt = 0; mt < 4; ++mt)
                #pragma unroll
                for (int nt = 0; nt < 4; ++nt)
                    mma16816(acc[mt][nt], aH[mt], bH[nt][0], bH[nt][1]);
        }
    }

    const int g  = lane >> 2;
    const int cp = (lane & 3) * 2;
    const float al = *alphap;
    #pragma unroll
    for (int mt = 0; mt < 4; ++mt){
        #pragma unroll
        for (int nt = 0; nt < 4; ++nt){
            long n  = bn0 + wn * 32 + nt * 8 + cp;
            int  nc = (int)(n & 511);
            float b0 = bias[nc], b1 = bias[nc + 1];
            float* C = (n < 512) ? C0 : C1;
            #pragma unroll
            for (int h = 0; h < 2; ++h){
                long m = arow + wm * 64 + mt * 16 + g + h * 8;
                float v0 = acc[mt][nt][2*h + 0] + b0;
                float v1 = acc[mt][nt][2*h + 1] + b1;
                v0 = (v0 >= 0.f) ? v0 : al * v0;
                v1 = (v1 >= 0.f) ? v1 : al * v1;
                *(float2*)&C[m * 512 + nc] = make_float2(v0, v1);
                if (Hhi){
                    __half h0 = __float2half_rn(v0);
                    __half h1 = __float2half_rn(v1);
                    __half q0 = __float2half_rn(v0 - __half2float(h0));
                    __half q1 = __float2half_rn(v1 - __half2float(h1));
                    *(__half2*)&Hhi[m * 1024 + n] = __halves2half2(h0, h1);
                    *(__half2*)&Hlo[m * 1024 + n] = __halves2half2(q0, q1);
                }
            }
        }
    }
}

extern "C" void kernel_launch(void* const* d_in, const int* in_sizes, int n_in,
                              void* d_out, int out_size)
{
    const float* seq_pos = (const float*)d_in[0];
    const float* seq_neg = (const float*)d_in[1];
    const float* adj     = (const float*)d_in[2];
    const float* diff    = (const float*)d_in[3];
    const float* W1a = (const float*)d_in[4];
    const float* W1d = (const float*)d_in[5];
    const float* W2a = (const float*)d_in[6];
    const float* W2d = (const float*)d_in[7];
    const float* b1a = (const float*)d_in[8];
    const float* b1d = (const float*)d_in[9];
    const float* b2a = (const float*)d_in[10];
    const float* b2d = (const float*)d_in[11];
    const float* al1a = (const float*)d_in[12];
    const float* al1d = (const float*)d_in[13];
    const float* al2a = (const float*)d_in[14];
    const float* al2d = (const float*)d_in[15];

    float* out = (float*)d_out;
    const size_t CHN = (size_t)8192 * 512;

    __half *adjHi,*difHi,*spHi,*spLo,*snHi,*snLo,*wHi;
    __half *ftAHi,*ftDHi,*hAHi,*hALo,*hDHi,*hDLo;
    cudaGetSymbolAddress((void**)&adjHi, g_adjHi);
    cudaGetSymbolAddress((void**)&difHi, g_difHi);
    cudaGetSymbolAddress((void**)&spHi,  g_spHi);
    cudaGetSymbolAddress((void**)&spLo,  g_spLo);
    cudaGetSymbolAddress((void**)&snHi,  g_snHi);
    cudaGetSymbolAddress((void**)&snLo,  g_snLo);
    cudaGetSymbolAddress((void**)&wHi,   g_wHi);
    cudaGetSymbolAddress((void**)&ftAHi, g_ftAHi);
    cudaGetSymbolAddress((void**)&ftDHi, g_ftDHi);
    cudaGetSymbolAddress((void**)&hAHi,  g_hAHi);
    cudaGetSymbolAddress((void**)&hALo,  g_hALo);
    cudaGetSymbolAddress((void**)&hDHi,  g_hDHi);
    cudaGetSymbolAddress((void**)&hDLo,  g_hDLo);

    cudaFuncSetAttribute(gemm_small, cudaFuncAttributeMaxDynamicSharedMemorySize, SMEM_SMALL);
    cudaFuncSetAttribute(gemm_big,   cudaFuncAttributeMaxDynamicSharedMemorySize, SMEM_BIG);

    // one fused conversion launch
    {
        size_t total_vec4 = (2*NEL_ADJ + 2*NEL_SEQ + 4*NEL_W) / 4;
        int blocks = (int)((total_vec4 + 255) / 256);
        fused_split<<<blocks, 256>>>(adj, diff, seq_pos, seq_neg, W1a, W1d, W2a, W2d,
                                     adjHi, difHi, spHi, spLo, snHi, snLo, wHi);
    }

    dim3 blk(256);
    dim3 gS(4, 64, 4);   // 4 small gemms batched
    dim3 gB(8, 64, 2);   // 2 big gemms batched

    // layer 1 small: fts = seq @ W1 (pos cols 0-511, neg 512-1023)
    {
        SmallArgs a;
        a.Ahi[0]=spHi; a.Alo[0]=spLo; a.Ahi[1]=snHi; a.Alo[1]=snLo;
        a.Ahi[2]=spHi; a.Alo[2]=spLo; a.Ahi[3]=snHi; a.Alo[3]=snLo;
        for (int i=0;i<4;++i){ a.lda[i]=512; a.aofs[i]=0; }
        a.Bhi[0]=wHi+0*NEL_W; a.Bhi[1]=wHi+0*NEL_W;
        a.Bhi[2]=wHi+1*NEL_W; a.Bhi[3]=wHi+1*NEL_W;
        a.Fhi[0]=ftAHi; a.Fhi[1]=ftAHi; a.Fhi[2]=ftDHi; a.Fhi[3]=ftDHi;
        a.fcol[0]=0; a.fcol[1]=512; a.fcol[2]=0; a.fcol[3]=512;
        gemm_small<<<gS, blk, SMEM_SMALL>>>(a, 512, 512);
    }

    // layer 1 big: h1 = prelu(A @ fts + b), also emit h1 fp16 hi/lo
    {
        BigArgs a;
        a.Ahi[0]=adjHi; a.Ahi[1]=difHi;
        a.Bhi[0]=ftAHi; a.Bhi[1]=ftDHi;
        a.C0[0]=out+0*CHN; a.C1[0]=out+4*CHN;
        a.C0[1]=out+1*CHN; a.C1[1]=out+5*CHN;
        a.bias[0]=b1a; a.alphap[0]=al1a; a.bias[1]=b1d; a.alphap[1]=al1d;
        a.Hhi[0]=hAHi; a.Hlo[0]=hALo; a.Hhi[1]=hDHi; a.Hlo[1]=hDLo;
        gemm_big<<<gB, blk, SMEM_BIG>>>(a, 8192);
    }

    // layer 2 small: fts2 = h1 @ W2
    {
        SmallArgs a;
        a.Ahi[0]=hAHi; a.Alo[0]=hALo; a.Ahi[1]=hAHi; a.Alo[1]=hALo;
        a.Ahi[2]=hDHi; a.Alo[2]=hDLo; a.Ahi[3]=hDHi; a.Alo[3]=hDLo;
        for (int i=0;i<4;++i) a.lda[i]=1024;
        a.aofs[0]=0; a.aofs[1]=512; a.aofs[2]=0; a.aofs[3]=512;
        a.Bhi[0]=wHi+2*NEL_W; a.Bhi[1]=wHi+2*NEL_W;
        a.Bhi[2]=wHi+3*NEL_W; a.Bhi[3]=wHi+3*NEL_W;
        a.Fhi[0]=ftAHi; a.Fhi[1]=ftAHi; a.Fhi[2]=ftDHi; a.Fhi[3]=ftDHi;
        a.fcol[0]=0; a.fcol[1]=512; a.fcol[2]=0; a.fcol[3]=512;
        gemm_small<<<gS, blk, SMEM_SMALL>>>(a, 512, 512);
    }

    // layer 2 big
    {
        BigArgs a;
        a.Ahi[0]=adjHi; a.Ahi[1]=difHi;
        a.Bhi[0]=ftAHi; a.Bhi[1]=ftDHi;
        a.C0[0]=out+2*CHN; a.C1[0]=out+6*CHN;
        a.C0[1]=out+3*CHN; a.C1[1]=out+7*CHN;
        a.bias[0]=b2a; a.alphap[0]=al2a; a.bias[1]=b2d; a.alphap[1]=al2d;
        a.Hhi[0]=nullptr; a.Hlo[0]=nullptr; a.Hhi[1]=nullptr; a.Hlo[1]=nullptr;
        gemm_big<<<gB, blk, SMEM_BIG>>>(a, 8192);
    }
}

// round 17
// speedup vs baseline: 1.9481x; 1.0534x over previous
#include <cuda_runtime.h>
#include <cuda_fp16.h>
#include <stdint.h>

// Model_63256278335531: 2-layer dual-GCN via fp16 mma.sync (HMMA) GEMMs.
// All GEMMs single-term fp16 (D = Ah*Bh), fp32 register accumulate.
// Error budget: adj/seq/W/fts/h1 fp16 rounding terms sum (quadrature) to
// ~4.1e-4 relative, vs 1e-3 threshold.

#define NEL_ADJ (8192ull*8192ull)
#define NEL_SEQ (8192ull*512ull)
#define NEL_W   (512ull*512ull)
#define NEL_FTS (8192ull*1024ull)

__device__ __align__(16) __half g_adjHi[NEL_ADJ];
__device__ __align__(16) __half g_difHi[NEL_ADJ];
__device__ __align__(16) __half g_spHi[NEL_SEQ];
__device__ __align__(16) __half g_snHi[NEL_SEQ];
__device__ __align__(16) __half g_wHi[4][NEL_W];
// fts as B of big GEMM: [K=8192][N=1024] (pos cols 0-511, neg 512-1023)
__device__ __align__(16) __half g_ftAHi[NEL_FTS];
__device__ __align__(16) __half g_ftDHi[NEL_FTS];
// h1 packed [M=8192][1024]: A of layer-2 small GEMM
__device__ __align__(16) __half g_hAHi[NEL_FTS];
__device__ __align__(16) __half g_hDHi[NEL_FTS];

__device__ __forceinline__ uint32_t smem_u32(const void* p){
    uint32_t a;
    asm("{ .reg .u64 t; cvta.to.shared.u64 t, %1; cvt.u32.u64 %0, t; }"
        : "=r"(a) : "l"(p));
    return a;
}
__device__ __forceinline__ void cp16(uint32_t dst, const void* src){
    asm volatile("{ .reg .u64 g; cvta.to.global.u64 g, %1;"
                 " cp.async.cg.shared.global [%0], [g], 16; }"
                 :: "r"(dst), "l"(src) : "memory");
}
__device__ __forceinline__ void cp_commit(){
    asm volatile("cp.async.commit_group;" ::: "memory");
}
__device__ __forceinline__ void cp_wait1(){
    asm volatile("cp.async.wait_group 1;" ::: "memory");
}
__device__ __forceinline__ void ldsm_x4(uint32_t& r0, uint32_t& r1,
                                        uint32_t& r2, uint32_t& r3, uint32_t a){
    asm volatile("ldmatrix.sync.aligned.m8n8.x4.shared.b16 {%0,%1,%2,%3}, [%4];"
                 : "=r"(r0), "=r"(r1), "=r"(r2), "=r"(r3) : "r"(a));
}
__device__ __forceinline__ void ldsm_x4_t(uint32_t& r0, uint32_t& r1,
                                          uint32_t& r2, uint32_t& r3, uint32_t a){
    asm volatile("ldmatrix.sync.aligned.m8n8.x4.trans.shared.b16 {%0,%1,%2,%3}, [%4];"
                 : "=r"(r0), "=r"(r1), "=r"(r2), "=r"(r3) : "r"(a));
}
__device__ __forceinline__ void mma16816(float* c, const uint32_t* a,
                                         uint32_t b0, uint32_t b1){
    asm volatile("mma.sync.aligned.m16n8k16.row.col.f32.f16.f16.f32 "
                 "{%0,%1,%2,%3}, {%4,%5,%6,%7}, {%8,%9}, {%0,%1,%2,%3};"
                 : "+f"(c[0]), "+f"(c[1]), "+f"(c[2]), "+f"(c[3])
                 : "r"(a[0]), "r"(a[1]), "r"(a[2]), "r"(a[3]), "r"(b0), "r"(b1));
}

// ---- fused conversion: everything -> fp16 -----------------------------------
__device__ __forceinline__ void cv_hi(const float* __restrict__ x,
                                      __half* __restrict__ hi, size_t i)
{
    float4 v = *(const float4*)(x + i);
    __half2* H = (__half2*)(hi + i);
    H[0] = __halves2half2(__float2half_rn(v.x), __float2half_rn(v.y));
    H[1] = __halves2half2(__float2half_rn(v.z), __float2half_rn(v.w));
}

__global__ void fused_split(const float* __restrict__ adj, const float* __restrict__ dif,
                            const float* __restrict__ sp,  const float* __restrict__ sn,
                            const float* __restrict__ w0,  const float* __restrict__ w1,
                            const float* __restrict__ w2,  const float* __restrict__ w3,
                            __half* adjHi, __half* difHi,
                            __half* spHi, __half* snHi, __half* wHi)
{
    size_t o = ((size_t)blockIdx.x * blockDim.x + threadIdx.x) * 4;
    if (o < NEL_ADJ) { cv_hi(adj, adjHi, o); return; } o -= NEL_ADJ;
    if (o < NEL_ADJ) { cv_hi(dif, difHi, o); return; } o -= NEL_ADJ;
    if (o < NEL_SEQ) { cv_hi(sp, spHi, o); return; } o -= NEL_SEQ;
    if (o < NEL_SEQ) { cv_hi(sn, snHi, o); return; } o -= NEL_SEQ;
    if (o < NEL_W) { cv_hi(w0, wHi + 0*NEL_W, o); return; } o -= NEL_W;
    if (o < NEL_W) { cv_hi(w1, wHi + 1*NEL_W, o); return; } o -= NEL_W;
    if (o < NEL_W) { cv_hi(w2, wHi + 2*NEL_W, o); return; } o -= NEL_W;
    if (o < NEL_W) { cv_hi(w3, wHi + 3*NEL_W, o); }
}

// ---- GEMM core --------------------------------------------------------------
// CTA 128(M) x 128(N), K-stage 64, 3-stage cp.async pipeline, 1 sync/iter.
// 8 warps: wm = wid&1 (M-halves of 64), wn = wid>>1 (4 N-quarters of 32).
// A rows 128B (8x16B units), B rows 256B (16x16B units); unit swizzle u^(r&7).
// stage 32KB: AH@0 (16K)  BH@16K (16K) -> 3 stages = 96KB, 2 CTAs/SM.
#define STG_BYTES 32768
#define SMEM_DYN  (3*STG_BYTES)

struct SmallArgs {
    const __half* Ahi[4];
    long lda[4]; long aofs[4];
    const __half* Bhi[4];
    __half* Fhi[4];
    long fcol[4];
};
struct BigArgs {
    const __half* Ahi[2];
    const __half* Bhi[2];
    float* C0[2]; float* C1[2];
    const float* bias[2]; const float* alphap[2];
    __half* Hhi[2];
};

// small: fts[m*1024 + fcol + n] = fp16(A @ B), A fp16, B = W fp16, K=512
__global__ void __launch_bounds__(256, 2)
gemm_small(SmallArgs ar, int K, long ldb)
{
    extern __shared__ __align__(1024) char smem[];
    const uint32_t sbase = smem_u32(smem);
    const int z = blockIdx.z;
    const __half* __restrict__ Ahi = ar.Ahi[z];
    const __half* __restrict__ Bhi = ar.Bhi[z];
    __half* __restrict__ Fhi = ar.Fhi[z];
    const long lda = ar.lda[z], aofs = ar.aofs[z], fcol = ar.fcol[z];

    const int tid  = threadIdx.x;
    const int lane = tid & 31;
    const int wid  = tid >> 5;
    const int wm   = wid & 1;
    const int wn   = wid >> 1;
    const long arow = (long)blockIdx.y * 128;
    const long bn0  = (long)blockIdx.x * 128;
    const int  nk   = K >> 6;

    auto load_stage = [&](int st, int kc){
        uint32_t base = sbase + st * STG_BYTES;
        const long ka = aofs + (long)kc * 64;
        const long kb = (long)kc * 64;
        #pragma unroll
        for (int s = 0; s < 4; ++s){
            int idx = tid + 256 * s;
            int r = idx >> 3, u = idx & 7;
            uint32_t sw = (uint32_t)(r * 128 + ((u ^ (r & 7)) << 4));
            cp16(base + sw, Ahi + (arow + r) * lda + ka + u * 8);
        }
        #pragma unroll
        for (int s = 0; s < 4; ++s){
            int idx = tid + 256 * s;
            int r = idx >> 4, u = idx & 15;
            uint32_t sw = (uint32_t)(r * 256 + ((u ^ (r & 7)) << 4));
            cp16(base + 16384 + sw, Bhi + (kb + r) * ldb + bn0 + u * 8);
        }
        cp_commit();
    };

    float acc[4][4][4];
    #pragma unroll
    for (int i = 0; i < 4; ++i)
        #pragma unroll
        for (int j = 0; j < 4; ++j)
            #pragma unroll
            for (int q = 0; q < 4; ++q) acc[i][j][q] = 0.f;

    load_stage(0, 0);
    load_stage(1, 1);

    const int l16 = lane & 15, l2 = lane >> 4;
    const int bkr  = lane & 15;
    const int bnu0 = (wn * 32) >> 3;

    for (int kt = 0; kt < nk; ++kt){
        cp_wait1();
        __syncthreads();
        if (kt + 2 < nk) load_stage((kt + 2) % 3, kt + 2);
        else cp_commit();

        const uint32_t sb = sbase + (kt % 3) * STG_BYTES;
        #pragma unroll
        for (int ks = 0; ks < 4; ++ks){
            uint32_t aH[4][4], bH[4][2];
            #pragma unroll
            for (int mt = 0; mt < 4; ++mt){
                int mr = wm * 64 + mt * 16 + l16;
                uint32_t ad = sb + mr * 128 + (((ks * 2 + l2) ^ (mr & 7)) << 4);
                ldsm_x4(aH[mt][0], aH[mt][1], aH[mt][2], aH[mt][3], ad);
            }
            #pragma unroll
            for (int p = 0; p < 2; ++p){
                int kr = ks * 16 + bkr;
                int nu = bnu0 + p * 2 + l2;
                uint32_t ad = sb + 16384 + kr * 256 + ((nu ^ (kr & 7)) << 4);
                ldsm_x4_t(bH[2*p][0], bH[2*p][1], bH[2*p+1][0], bH[2*p+1][1], ad);
            }
            #pragma unroll
            for (int mt = 0; mt < 4; ++mt)
                #pragma unroll
                for (int nt = 0; nt < 4; ++nt)
                    mma16816(acc[mt][nt], aH[mt], bH[nt][0], bH[nt][1]);
        }
    }

    const int g  = lane >> 2;
    const int cp = (lane & 3) * 2;
    #pragma unroll
    for (int mt = 0; mt < 4; ++mt){
        #pragma unroll
        for (int nt = 0; nt < 4; ++nt){
            long n = fcol + bn0 + wn * 32 + nt * 8 + cp;
            #pragma unroll
            for (int h = 0; h < 2; ++h){
                long m = arow + wm * 64 + mt * 16 + g + h * 8;
                float v0 = acc[mt][nt][2*h + 0];
                float v1 = acc[mt][nt][2*h + 1];
                *(__half2*)&Fhi[m * 1024 + n] =
                    __halves2half2(__float2half_rn(v0), __float2half_rn(v1));
            }
        }
    }
}

// big: prelu(A@B + bias) -> fp32 C0/C1 (split at n=512), optional h1 fp16.
// A = adj/diff fp16, B = fts fp16. K=8192, lda=8192, ldb=1024.
__global__ void __launch_bounds__(256, 2)
gemm_big(BigArgs ar, int K)
{
    extern __shared__ __align__(1024) char smem[];
    const uint32_t sbase = smem_u32(smem);
    const int z = blockIdx.z;
    const __half* __restrict__ Ahi = ar.Ahi[z];
    const __half* __restrict__ Bhi = ar.Bhi[z];
    float* __restrict__ C0 = ar.C0[z];
    float* __restrict__ C1 = ar.C1[z];
    const float* __restrict__ bias = ar.bias[z];
    const float* __restrict__ alphap = ar.alphap[z];
    __half* __restrict__ Hhi = ar.Hhi[z];
    const long lda = 8192, ldb = 1024;

    const int tid  = threadIdx.x;
    const int lane = tid & 31;
    const int wid  = tid >> 5;
    const int wm   = wid & 1;
    const int wn   = wid >> 1;
    const long arow = (long)blockIdx.y * 128;
    const long bn0  = (long)blockIdx.x * 128;
    const int  nk   = K >> 6;

    auto load_stage = [&](int st, int kc){
        uint32_t base = sbase + st * STG_BYTES;
        const long ka = (long)kc * 64;
        const long kb = (long)kc * 64;
        #pragma unroll
        for (int s = 0; s < 4; ++s){
            int idx = tid + 256 * s;
            int r = idx >> 3, u = idx & 7;
            uint32_t sw = (uint32_t)(r * 128 + ((u ^ (r & 7)) << 4));
            cp16(base + sw, Ahi + (arow + r) * lda + ka + u * 8);
        }
        #pragma unroll
        for (int s = 0; s < 4; ++s){
            int idx = tid + 256 * s;
            int r = idx >> 4, u = idx & 15;
            uint32_t sw = (uint32_t)(r * 256 + ((u ^ (r & 7)) << 4));
            cp16(base + 16384 + sw, Bhi + (kb + r) * ldb + bn0 + u * 8);
        }
        cp_commit();
    };

    float acc[4][4][4];
    #pragma unroll
    for (int i = 0; i < 4; ++i)
        #pragma unroll
        for (int j = 0; j < 4; ++j)
            #pragma unroll
            for (int q = 0; q < 4; ++q) acc[i][j][q] = 0.f;

    load_stage(0, 0);
    load_stage(1, 1);

    const int l16 = lane & 15, l2 = lane >> 4;
    const int bkr  = lane & 15;
    const int bnu0 = (wn * 32) >> 3;

    for (int kt = 0; kt < nk; ++kt){
        cp_wait1();
        __syncthreads();
        if (kt + 2 < nk) load_stage((kt + 2) % 3, kt + 2);
        else cp_commit();

        const uint32_t sb = sbase + (kt % 3) * STG_BYTES;
        #pragma unroll
        for (int ks = 0; ks < 4; ++ks){
            uint32_t aH[4][4], bH[4][2];
            #pragma unroll
            for (int mt = 0; mt < 4; ++mt){
                int mr = wm * 64 + mt * 16 + l16;
                uint32_t ad = sb + mr * 128 + (((ks * 2 + l2) ^ (mr & 7)) << 4);
                ldsm_x4(aH[mt][0], aH[mt][1], aH[mt][2], aH[mt][3], ad);
            }
            #pragma unroll
            for (int p = 0; p < 2; ++p){
                int kr = ks * 16 + bkr;
                int nu = bnu0 + p * 2 + l2;
                uint32_t ad = sb + 16384 + kr * 256 + ((nu ^ (kr & 7)) << 4);
                ldsm_x4_t(bH[2*p][0], bH[2*p][1], bH[2*p+1][0], bH[2*p+1][1], ad);
            }
            #pragma unroll
            for (int mt = 0; mt < 4; ++mt)
                #pragma unroll
                for (int nt = 0; nt < 4; ++nt)
                    mma16816(acc[mt][nt], aH[mt], bH[nt][0], bH[nt][1]);
        }
    }

    const int g  = lane >> 2;
    const int cp = (lane & 3) * 2;
    const float al = *alphap;
    #pragma unroll
    for (int mt = 0; mt < 4; ++mt){
        #pragma unroll
        for (int nt = 0; nt < 4; ++nt){
            long n  = bn0 + wn * 32 + nt * 8 + cp;
            int  nc = (int)(n & 511);
            float b0 = bias[nc], b1 = bias[nc + 1];
            float* C = (n < 512) ? C0 : C1;
            #pragma unroll
            for (int h = 0; h < 2; ++h){
                long m = arow + wm * 64 + mt * 16 + g + h * 8;
                float v0 = acc[mt][nt][2*h + 0] + b0;
                float v1 = acc[mt][nt][2*h + 1] + b1;
                v0 = (v0 >= 0.f) ? v0 : al * v0;
                v1 = (v1 >= 0.f) ? v1 : al * v1;
                *(float2*)&C[m * 512 + nc] = make_float2(v0, v1);
                if (Hhi){
                    *(__half2*)&Hhi[m * 1024 + n] =
                        __halves2half2(__float2half_rn(v0), __float2half_rn(v1));
                }
            }
        }
    }
}

extern "C" void kernel_launch(void* const* d_in, const int* in_sizes, int n_in,
                              void* d_out, int out_size)
{
    const float* seq_pos = (const float*)d_in[0];
    const float* seq_neg = (const float*)d_in[1];
    const float* adj     = (const float*)d_in[2];
    const float* diff    = (const float*)d_in[3];
    const float* W1a = (const float*)d_in[4];
    const float* W1d = (const float*)d_in[5];
    const float* W2a = (const float*)d_in[6];
    const float* W2d = (const float*)d_in[7];
    const float* b1a = (const float*)d_in[8];
    const float* b1d = (const float*)d_in[9];
    const float* b2a = (const float*)d_in[10];
    const float* b2d = (const float*)d_in[11];
    const float* al1a = (const float*)d_in[12];
    const float* al1d = (const float*)d_in[13];
    const float* al2a = (const float*)d_in[14];
    const float* al2d = (const float*)d_in[15];

    float* out = (float*)d_out;
    const size_t CHN = (size_t)8192 * 512;

    __half *adjHi,*difHi,*spHi,*snHi,*wHi;
    __half *ftAHi,*ftDHi,*hAHi,*hDHi;
    cudaGetSymbolAddress((void**)&adjHi, g_adjHi);
    cudaGetSymbolAddress((void**)&difHi, g_difHi);
    cudaGetSymbolAddress((void**)&spHi,  g_spHi);
    cudaGetSymbolAddress((void**)&snHi,  g_snHi);
    cudaGetSymbolAddress((void**)&wHi,   g_wHi);
    cudaGetSymbolAddress((void**)&ftAHi, g_ftAHi);
    cudaGetSymbolAddress((void**)&ftDHi, g_ftDHi);
    cudaGetSymbolAddress((void**)&hAHi,  g_hAHi);
    cudaGetSymbolAddress((void**)&hDHi,  g_hDHi);

    cudaFuncSetAttribute(gemm_small, cudaFuncAttributeMaxDynamicSharedMemorySize, SMEM_DYN);
    cudaFuncSetAttribute(gemm_big,   cudaFuncAttributeMaxDynamicSharedMemorySize, SMEM_DYN);

    // one fused conversion launch
    {
        size_t total_vec4 = (2*NEL_ADJ + 2*NEL_SEQ + 4*NEL_W) / 4;
        int blocks = (int)((total_vec4 + 255) / 256);
        fused_split<<<blocks, 256>>>(adj, diff, seq_pos, seq_neg, W1a, W1d, W2a, W2d,
                                     adjHi, difHi, spHi, snHi, wHi);
    }

    dim3 blk(256);
    dim3 gS(4, 64, 4);   // 4 small gemms batched
    dim3 gB(8, 64, 2);   // 2 big gemms batched

    // layer 1 small: fts = seq @ W1 (pos cols 0-511, neg 512-1023)
    {
        SmallArgs a;
        a.Ahi[0]=spHi; a.Ahi[1]=snHi; a.Ahi[2]=spHi; a.Ahi[3]=snHi;
        for (int i=0;i<4;++i){ a.lda[i]=512; a.aofs[i]=0; }
        a.Bhi[0]=wHi+0*NEL_W; a.Bhi[1]=wHi+0*NEL_W;
        a.Bhi[2]=wHi+1*NEL_W; a.Bhi[3]=wHi+1*NEL_W;
        a.Fhi[0]=ftAHi; a.Fhi[1]=ftAHi; a.Fhi[2]=ftDHi; a.Fhi[3]=ftDHi;
        a.fcol[0]=0; a.fcol[1]=512; a.fcol[2]=0; a.fcol[3]=512;
        gemm_small<<<gS, blk, SMEM_DYN>>>(a, 512, 512);
    }

    // layer 1 big: h1 = prelu(A @ fts + b), also emit h1 fp16
    {
        BigArgs a;
        a.Ahi[0]=adjHi; a.Ahi[1]=difHi;
        a.Bhi[0]=ftAHi; a.Bhi[1]=ftDHi;
        a.C0[0]=out+0*CHN; a.C1[0]=out+4*CHN;
        a.C0[1]=out+1*CHN; a.C1[1]=out+5*CHN;
        a.bias[0]=b1a; a.alphap[0]=al1a; a.bias[1]=b1d; a.alphap[1]=al1d;
        a.Hhi[0]=hAHi; a.Hhi[1]=hDHi;
        gemm_big<<<gB, blk, SMEM_DYN>>>(a, 8192);
    }

    // layer 2 small: fts2 = h1 @ W2
    {
        SmallArgs a;
        a.Ahi[0]=hAHi; a.Ahi[1]=hAHi; a.Ahi[2]=hDHi; a.Ahi[3]=hDHi;
        for (int i=0;i<4;++i) a.lda[i]=1024;
        a.aofs[0]=0; a.aofs[1]=512; a.aofs[2]=0; a.aofs[3]=512;
        a.Bhi[0]=wHi+2*NEL_W; a.Bhi[1]=wHi+2*NEL_W;
        a.Bhi[2]=wHi+3*NEL_W; a.Bhi[3]=wHi+3*NEL_W;
        a.Fhi[0]=ftAHi; a.Fhi[1]=ftAHi; a.Fhi[2]=ftDHi; a.Fhi[3]=ftDHi;
        a.fcol[0]=0; a.fcol[1]=512; a.fcol[2]=0; a.fcol[3]=512;
        gemm_small<<<gS, blk, SMEM_DYN>>>(a, 512, 512);
    }

    // layer 2 big
    {
        BigArgs a;
        a.Ahi[0]=adjHi; a.Ahi[1]=difHi;
        a.Bhi[0]=ftAHi; a.Bhi[1]=ftDHi;
        a.C0[0]=out+2*CHN; a.C1[0]=out+6*CHN;
        a.C0[1]=out+3*CHN; a.C1[1]=out+7*CHN;
        a.bias[0]=b2a; a.alphap[0]=al2a; a.bias[1]=b2d; a.alphap[1]=al2d;
        a.Hhi[0]=nullptr; a.Hhi[1]=nullptr;
        gemm_big<<<gB, blk, SMEM_DYN>>>(a, 8192);
    }
}